// round 15
// baseline (speedup 1.0000x reference)
#include <cuda_runtime.h>
#include <cuda_bf16.h>
#include <cstdint>

// Sizes fixed by the problem
#define B_  64
#define C_  256
#define W_  256
#define E_  2048
#define D_  2048
#define MTOT 16384            // B_*W_

// ---------------- static scratch (no runtime allocation allowed) ----------
__device__ __nv_bfloat16 g_xbf[(size_t)MTOT * E_]; // x_txt bf16 (64MB)
__device__ __nv_bfloat16 g_wbf[(size_t)D_ * E_];   // W_words1 bf16 (8MB)
__device__ float g_ldrp[8 * B_ * D_];              // leader k-split partials
__device__ float g_ldr[B_ * D_];                   // leader vectors fp32
__device__ int   g_idx[B_];                        // argmax indices
__device__ float g_dpp[16][MTOT];                  // dp partials per n-tile
__device__ float g_sqp[16][MTOT];                  // sq partials per n-tile

__device__ __forceinline__ uint32_t smem_u32(const void* p) {
    uint32_t a;
    asm("{ .reg .u64 t; cvta.to.shared.u64 t, %1; cvt.u32.u64 %0, t; }" : "=r"(a) : "l"(p));
    return a;
}
#define CP16(dst, src) \
    asm volatile("cp.async.cg.shared.global [%0], [%1], 16;" :: "r"(dst), "l"(src))
#define CP_COMMIT() asm volatile("cp.async.commit_group;" ::: "memory")
#define CP_WAIT1()  asm volatile("cp.async.wait_group 1;" ::: "memory")
#define CP_WAIT0()  asm volatile("cp.async.wait_group 0;" ::: "memory")

// =========================== K1: convert + argmax =========================
__global__ void __launch_bounds__(256) k1_prep(const float* __restrict__ y,
                                               const float* __restrict__ xt,
                                               const float* __restrict__ ww) {
    int t = threadIdx.x;
    if (blockIdx.x < B_) {
        __shared__ float sv[256];
        __shared__ int   si[256];
        int b = blockIdx.x;
        sv[t] = y[b * C_ + t]; si[t] = t;
        __syncthreads();
        for (int s = 128; s > 0; s >>= 1) {
            if (t < s) {
                float v2 = sv[t + s];
                if (v2 > sv[t] || (v2 == sv[t] && si[t + s] < si[t])) { sv[t] = v2; si[t] = si[t + s]; }
            }
            __syncthreads();
        }
        if (t == 0) g_idx[b] = si[0];
    }
    size_t gid = (size_t)blockIdx.x * 256 + t;
    size_t stride = (size_t)gridDim.x * 256;
    const float4* x4 = (const float4*)xt;
    uint2* xo = (uint2*)g_xbf;
    for (size_t i = gid; i < (size_t)MTOT * E_ / 4; i += stride) {
        float4 v = x4[i];
        union { __nv_bfloat162 h[2]; uint2 u; } p;
        p.h[0] = __floats2bfloat162_rn(v.x, v.y);
        p.h[1] = __floats2bfloat162_rn(v.z, v.w);
        xo[i] = p.u;
    }
    const float4* w4 = (const float4*)ww;
    uint2* wo = (uint2*)g_wbf;
    for (size_t i = gid; i < (size_t)D_ * E_ / 4; i += stride) {
        float4 v = w4[i];
        union { __nv_bfloat162 h[2]; uint2 u; } p;
        p.h[0] = __floats2bfloat162_rn(v.x, v.y);
        p.h[1] = __floats2bfloat162_rn(v.z, v.w);
        wo[i] = p.u;
    }
}

// ================= K2: leader partial GEMM  W_img1 @ x_sel ================
__global__ void __launch_bounds__(256) k2_leader(const float* __restrict__ x_img,
                                                 const float* __restrict__ W_img) {
    __shared__ float Wt[128][33];
    __shared__ float Xt[64][33];
    const int d0 = blockIdx.x * 128;
    const int ks = blockIdx.y;
    const int t = threadIdx.x;
    const int dg = t & 15, bg = t >> 4;
    float acc[8][4];
#pragma unroll
    for (int i = 0; i < 8; i++)
#pragma unroll
        for (int j = 0; j < 4; j++) acc[i][j] = 0.f;

    for (int sub = 0; sub < 8; ++sub) {
        const int k0 = ks * 256 + sub * 32;
        __syncthreads();
#pragma unroll
        for (int j = 0; j < 4; ++j) {
            int e = t + j * 256, row = e >> 3, c4 = e & 7;
            float4 v = *(const float4*)&W_img[(size_t)(d0 + row) * E_ + k0 + c4 * 4];
            Wt[row][c4 * 4 + 0] = v.x; Wt[row][c4 * 4 + 1] = v.y;
            Wt[row][c4 * 4 + 2] = v.z; Wt[row][c4 * 4 + 3] = v.w;
        }
#pragma unroll
        for (int j = 0; j < 2; ++j) {
            int e = t + j * 256, row = e >> 3, c4 = e & 7;
            int src = row * C_ + g_idx[row];
            float4 v = *(const float4*)&x_img[(size_t)src * E_ + k0 + c4 * 4];
            Xt[row][c4 * 4 + 0] = v.x; Xt[row][c4 * 4 + 1] = v.y;
            Xt[row][c4 * 4 + 2] = v.z; Xt[row][c4 * 4 + 3] = v.w;
        }
        __syncthreads();
#pragma unroll 8
        for (int k = 0; k < 32; ++k) {
            float xv[4];
#pragma unroll
            for (int j = 0; j < 4; j++) xv[j] = Xt[bg * 4 + j][k];
#pragma unroll
            for (int i = 0; i < 8; i++) {
                float wv = Wt[dg + i * 16][k];
#pragma unroll
                for (int j = 0; j < 4; j++) acc[i][j] += wv * xv[j];
            }
        }
    }
    float* outp = g_ldrp + (size_t)ks * (B_ * D_);
#pragma unroll
    for (int i = 0; i < 8; i++)
#pragma unroll
        for (int j = 0; j < 4; j++)
            outp[(bg * 4 + j) * D_ + d0 + dg + i * 16] = acc[i][j];
}

__global__ void __launch_bounds__(256) k2b_reduce(const float* __restrict__ b_img) {
    int i = blockIdx.x * 256 + threadIdx.x;
    float s = b_img[i & (D_ - 1)];
#pragma unroll
    for (int ks = 0; ks < 8; ++ks) s += g_ldrp[ks * (B_ * D_) + i];
    g_ldr[i] = s;
}

// ========== K3: fused bf16 GEMM (mma.sync) -> g_dpp, g_sqp ================
// Grid = 2048 CTAs: 128 m-tiles x 16 n-tiles. CTA tile M=128 x N=128 over
// full K=2048, BK=64, 3-stage cp.async pipeline, one __syncthreads/stage.
// Warp tile M32 x N64, __launch_bounds__(256, 2) -> 2 CTAs/SM (16 warps).
// NEW: warps 4-7 process ks in rotated order (2,3,0,1) so the two warps
// sharing each SMSP are anti-phased: one runs MMAs while the other does
// LDSM, keeping the tensor unit fed through fragment-load windows.
#define ROWB   144                   // bytes per smem row (64 bf16 + pad)
#define STG_A  (128 * ROWB)          // 18432 B
#define STG_B  (128 * ROWB)          // 18432 B
#define KSTEPS 32                    // 32 k-steps of BK=64
#define SMEM_DYN (3 * (STG_A + STG_B))   // 110592 B

__device__ __forceinline__ void k3_load_stage(uint32_t sA, uint32_t sB, int s,
                                              const __nv_bfloat16* Abase,
                                              const __nv_bfloat16* Bbase, int t) {
    const int k0 = s * 64;
    const uint32_t aB = sA + (s % 3) * STG_A;
    const uint32_t bB = sB + (s % 3) * STG_B;
    const __nv_bfloat16* Ag = Abase + k0;
    const __nv_bfloat16* Bg = Bbase + k0;
#pragma unroll
    for (int j = 0; j < 4; ++j) {                  // A: 128 rows x 8 chunks
        int id = j * 256 + t, row = id >> 3, ch = id & 7;
        CP16(aB + row * ROWB + ch * 16, Ag + (size_t)row * E_ + ch * 8);
    }
#pragma unroll
    for (int j = 0; j < 4; ++j) {                  // B: 128 rows x 8 chunks
        int id = j * 256 + t, row = id >> 3, ch = id & 7;
        CP16(bB + row * ROWB + ch * 16, Bg + (size_t)row * E_ + ch * 8);
    }
    CP_COMMIT();
}

__global__ void __launch_bounds__(256, 2) k3_gemm(const float* __restrict__ bwrd) {
    extern __shared__ __align__(16) char dyn[];
    __shared__ float sDp[2][128], sSq[2][128];

    const int t = threadIdx.x, lane = t & 31, warp = t >> 5;
    const int u = blockIdx.x;
    const int mt = u >> 4;                         // 0..127 m-tile
    const int nt = u & 15;                         // 0..15 n-tile (fixed per CTA)
    const int m0 = mt * 128;
    const int n0 = nt * 128;
    const int bidx = mt >> 1;                      // batch index
    const int mrow = (warp & 3) * 32;              // warp m-origin (M32)
    const int wn = warp >> 2;                      // 0..1
    const int ncol = wn * 64;                      // warp n-origin (N64)
    const int kofs = (warp >> 2) & 1 ? 2 : 0;      // anti-phase ks schedule
    const __nv_bfloat16* Abase = g_xbf + (size_t)m0 * E_;
    const __nv_bfloat16* Bbase = g_wbf + (size_t)n0 * E_;
    const float* ldrb = g_ldr + bidx * D_;

    const uint32_t sA = smem_u32(dyn);
    const uint32_t sB = sA + 3 * STG_A;

    float acc[2][8][4];                            // mi(2 x m16) x nj(8 x n8) x frag
#pragma unroll
    for (int mi = 0; mi < 2; ++mi)
#pragma unroll
        for (int nj = 0; nj < 8; ++nj)
#pragma unroll
            for (int c = 0; c < 4; ++c) acc[mi][nj][c] = 0.f;

    k3_load_stage(sA, sB, 0, Abase, Bbase, t);
    k3_load_stage(sA, sB, 1, Abase, Bbase, t);

#pragma unroll 1
    for (int s = 0; s < KSTEPS; ++s) {
        if (s + 1 < KSTEPS) CP_WAIT1(); else CP_WAIT0();
        __syncthreads();
        if (s + 2 < KSTEPS) k3_load_stage(sA, sB, s + 2, Abase, Bbase, t);

        const uint32_t aB = sA + (s % 3) * STG_A;
        const uint32_t bB = sB + (s % 3) * STG_B;

#pragma unroll
        for (int ks = 0; ks < 4; ++ks) {
            const int ksx = (ks + kofs) & 3;       // per-warp rotated k order
            uint32_t a[2][4];
            uint32_t b[4][4];
#pragma unroll
            for (int mi = 0; mi < 2; ++mi) {
                uint32_t addr = aB + (mrow + mi * 16 + (lane & 15)) * ROWB
                              + ksx * 32 + ((lane >> 4) << 4);
                asm volatile("ldmatrix.sync.aligned.m8n8.x4.shared.b16 {%0,%1,%2,%3}, [%4];"
                             : "=r"(a[mi][0]), "=r"(a[mi][1]), "=r"(a[mi][2]), "=r"(a[mi][3])
                             : "r"(addr));
            }
#pragma unroll
            for (int ng = 0; ng < 4; ++ng) {
                uint32_t addr = bB + (ncol + ng * 16 + ((lane >> 4) << 3) + (lane & 7)) * ROWB
                              + ksx * 32 + (((lane >> 3) & 1) << 4);
                asm volatile("ldmatrix.sync.aligned.m8n8.x4.shared.b16 {%0,%1,%2,%3}, [%4];"
                             : "=r"(b[ng][0]), "=r"(b[ng][1]), "=r"(b[ng][2]), "=r"(b[ng][3])
                             : "r"(addr));
            }
#pragma unroll
            for (int ng = 0; ng < 4; ++ng) {
#pragma unroll
                for (int mi = 0; mi < 2; ++mi) {
                    asm volatile("mma.sync.aligned.m16n8k16.row.col.f32.bf16.bf16.f32 "
                                 "{%0,%1,%2,%3}, {%4,%5,%6,%7}, {%8,%9}, {%0,%1,%2,%3};"
                                 : "+f"(acc[mi][ng * 2][0]), "+f"(acc[mi][ng * 2][1]),
                                   "+f"(acc[mi][ng * 2][2]), "+f"(acc[mi][ng * 2][3])
                                 : "r"(a[mi][0]), "r"(a[mi][1]), "r"(a[mi][2]), "r"(a[mi][3]),
                                   "r"(b[ng][0]), "r"(b[ng][1]));
                    asm volatile("mma.sync.aligned.m16n8k16.row.col.f32.bf16.bf16.f32 "
                                 "{%0,%1,%2,%3}, {%4,%5,%6,%7}, {%8,%9}, {%0,%1,%2,%3};"
                                 : "+f"(acc[mi][ng * 2 + 1][0]), "+f"(acc[mi][ng * 2 + 1][1]),
                                   "+f"(acc[mi][ng * 2 + 1][2]), "+f"(acc[mi][ng * 2 + 1][3])
                                 : "r"(a[mi][0]), "r"(a[mi][1]), "r"(a[mi][2]), "r"(a[mi][3]),
                                   "r"(b[ng][2]), "r"(b[ng][3]));
                }
            }
        }
    }

    // -------- fused epilogue (once per CTA): bias + dp/sq ----------------
    float dp[4], sq[4];
#pragma unroll
    for (int i = 0; i < 4; ++i) { dp[i] = 0.f; sq[i] = 0.f; }
#pragma unroll
    for (int nj = 0; nj < 8; ++nj) {
        const int n = n0 + ncol + nj * 8 + (lane & 3) * 2;
        const float bi0 = bwrd[n], bi1 = bwrd[n + 1];
        const float l0 = ldrb[n], l1 = ldrb[n + 1];
#pragma unroll
        for (int mi = 0; mi < 2; ++mi) {
            float v0 = acc[mi][nj][0] + bi0;
            float v1 = acc[mi][nj][1] + bi1;
            float v2 = acc[mi][nj][2] + bi0;
            float v3 = acc[mi][nj][3] + bi1;
            dp[mi * 2 + 0] = fmaf(v0, l0, dp[mi * 2 + 0]);
            dp[mi * 2 + 0] = fmaf(v1, l1, dp[mi * 2 + 0]);
            sq[mi * 2 + 0] = fmaf(v0, v0, sq[mi * 2 + 0]);
            sq[mi * 2 + 0] = fmaf(v1, v1, sq[mi * 2 + 0]);
            dp[mi * 2 + 1] = fmaf(v2, l0, dp[mi * 2 + 1]);
            dp[mi * 2 + 1] = fmaf(v3, l1, dp[mi * 2 + 1]);
            sq[mi * 2 + 1] = fmaf(v2, v2, sq[mi * 2 + 1]);
            sq[mi * 2 + 1] = fmaf(v3, v3, sq[mi * 2 + 1]);
        }
    }

    // reduce the 4 lanes (lane&3) sharing each row, then combine n-groups
#pragma unroll
    for (int off = 1; off < 4; off <<= 1) {
#pragma unroll
        for (int i = 0; i < 4; ++i) {
            dp[i] += __shfl_xor_sync(0xffffffffu, dp[i], off);
            sq[i] += __shfl_xor_sync(0xffffffffu, sq[i], off);
        }
    }
    if ((lane & 3) == 0) {
#pragma unroll
        for (int mi = 0; mi < 2; ++mi)
#pragma unroll
            for (int p = 0; p < 2; ++p) {
                int r = mrow + mi * 16 + (lane >> 2) + p * 8;
                sDp[wn][r] = dp[mi * 2 + p];
                sSq[wn][r] = sq[mi * 2 + p];
            }
    }
    __syncthreads();
    if (t < 128) {
        g_dpp[nt][m0 + t] = sDp[0][t] + sDp[1][t];
        g_sqp[nt][m0 + t] = sSq[0][t] + sSq[1][t];
    }
}

// ================= K4: combine partials + norm + cosine + softmax =========
__global__ void __launch_bounds__(256) k4_softmax(float* __restrict__ out) {
    __shared__ float red[256];
    __shared__ float bcast;
    const int b = blockIdx.x, t = threadIdx.x;
    float s = 0.f;
    for (int i = t; i < D_; i += 256) { float v = g_ldr[b * D_ + i]; s += v * v; }
    red[t] = s; __syncthreads();
    for (int st = 128; st > 0; st >>= 1) { if (t < st) red[t] += red[t + st]; __syncthreads(); }
    if (t == 0) bcast = sqrtf(red[0]);
    __syncthreads();
    const float lnorm = bcast;
    const int m = b * W_ + t;
    float dpv = 0.f, sqv = 0.f;
#pragma unroll
    for (int ntl = 0; ntl < 16; ++ntl) { dpv += g_dpp[ntl][m]; sqv += g_sqp[ntl][m]; }
    float dn = lnorm * sqrtf(fmaxf(sqv, 0.f));
    float logit = dpv / fmaxf(dn, 1e-8f);
    __syncthreads();
    red[t] = logit; __syncthreads();
    for (int st = 128; st > 0; st >>= 1) { if (t < st) red[t] = fmaxf(red[t], red[t + st]); __syncthreads(); }
    float mx = red[0]; __syncthreads();
    float e = expf(logit - mx);
    red[t] = e; __syncthreads();
    for (int st = 128; st > 0; st >>= 1) { if (t < st) red[t] += red[t + st]; __syncthreads(); }
    out[m] = e / red[0];
}

// ===========================================================================
extern "C" void kernel_launch(void* const* d_in, const int* in_sizes, int n_in,
                              void* d_out, int out_size) {
    const float* x_img = (const float*)d_in[0];   // [64,256,2048]
    const float* x_txt = (const float*)d_in[1];   // [64,256,2048]
    const float* y     = (const float*)d_in[2];   // [64,256]
    const float* W_img = (const float*)d_in[3];   // [2048,2048]
    const float* b_img = (const float*)d_in[4];   // [2048]
    const float* W_wrd = (const float*)d_in[5];   // [2048,2048]
    const float* b_wrd = (const float*)d_in[6];   // [2048]
    float* out = (float*)d_out;                   // [64,256]

    cudaFuncSetAttribute(k3_gemm, cudaFuncAttributeMaxDynamicSharedMemorySize, SMEM_DYN);

    k1_prep<<<2048, 256>>>(y, x_txt, W_wrd);
    k2_leader<<<dim3(16, 8), 256>>>(x_img, W_img);
    k2b_reduce<<<512, 256>>>(b_img);
    k3_gemm<<<2048, 256, SMEM_DYN>>>(b_wrd);
    k4_softmax<<<B_, 256>>>(out);
}

// round 16
// speedup vs baseline: 1.1215x; 1.1215x over previous
#include <cuda_runtime.h>
#include <cuda_bf16.h>
#include <cstdint>

// Sizes fixed by the problem
#define B_  64
#define C_  256
#define W_  256
#define E_  2048
#define D_  2048
#define MTOT 16384            // B_*W_

// ---------------- static scratch (no runtime allocation allowed) ----------
__device__ __nv_bfloat16 g_xbf[(size_t)MTOT * E_]; // x_txt bf16 (64MB)
__device__ __nv_bfloat16 g_wbf[(size_t)D_ * E_];   // W_words1 bf16 (8MB)
__device__ float g_ldrp[8 * B_ * D_];              // leader k-split partials
__device__ float g_ldr[B_ * D_];                   // leader vectors fp32
__device__ int   g_idx[B_];                        // argmax indices
__device__ float g_dpp[16][MTOT];                  // dp partials per n-tile
__device__ float g_sqp[16][MTOT];                  // sq partials per n-tile

__device__ __forceinline__ uint32_t smem_u32(const void* p) {
    uint32_t a;
    asm("{ .reg .u64 t; cvta.to.shared.u64 t, %1; cvt.u32.u64 %0, t; }" : "=r"(a) : "l"(p));
    return a;
}
#define CP16(dst, src) \
    asm volatile("cp.async.cg.shared.global [%0], [%1], 16;" :: "r"(dst), "l"(src))
#define CP_COMMIT() asm volatile("cp.async.commit_group;" ::: "memory")
#define CP_WAIT1()  asm volatile("cp.async.wait_group 1;" ::: "memory")
#define CP_WAIT0()  asm volatile("cp.async.wait_group 0;" ::: "memory")

// =========================== K1: convert + argmax =========================
__global__ void __launch_bounds__(256) k1_prep(const float* __restrict__ y,
                                               const float* __restrict__ xt,
                                               const float* __restrict__ ww) {
    int t = threadIdx.x;
    if (blockIdx.x < B_) {
        __shared__ float sv[256];
        __shared__ int   si[256];
        int b = blockIdx.x;
        sv[t] = y[b * C_ + t]; si[t] = t;
        __syncthreads();
        for (int s = 128; s > 0; s >>= 1) {
            if (t < s) {
                float v2 = sv[t + s];
                if (v2 > sv[t] || (v2 == sv[t] && si[t + s] < si[t])) { sv[t] = v2; si[t] = si[t + s]; }
            }
            __syncthreads();
        }
        if (t == 0) g_idx[b] = si[0];
    }
    size_t gid = (size_t)blockIdx.x * 256 + t;
    size_t stride = (size_t)gridDim.x * 256;
    const float4* x4 = (const float4*)xt;
    uint2* xo = (uint2*)g_xbf;
    for (size_t i = gid; i < (size_t)MTOT * E_ / 4; i += stride) {
        float4 v = x4[i];
        union { __nv_bfloat162 h[2]; uint2 u; } p;
        p.h[0] = __floats2bfloat162_rn(v.x, v.y);
        p.h[1] = __floats2bfloat162_rn(v.z, v.w);
        xo[i] = p.u;
    }
    const float4* w4 = (const float4*)ww;
    uint2* wo = (uint2*)g_wbf;
    for (size_t i = gid; i < (size_t)D_ * E_ / 4; i += stride) {
        float4 v = w4[i];
        union { __nv_bfloat162 h[2]; uint2 u; } p;
        p.h[0] = __floats2bfloat162_rn(v.x, v.y);
        p.h[1] = __floats2bfloat162_rn(v.z, v.w);
        wo[i] = p.u;
    }
}

// ================= K2: leader partial GEMM  W_img1 @ x_sel ================
__global__ void __launch_bounds__(256) k2_leader(const float* __restrict__ x_img,
                                                 const float* __restrict__ W_img) {
    __shared__ float Wt[128][33];
    __shared__ float Xt[64][33];
    const int d0 = blockIdx.x * 128;
    const int ks = blockIdx.y;
    const int t = threadIdx.x;
    const int dg = t & 15, bg = t >> 4;
    float acc[8][4];
#pragma unroll
    for (int i = 0; i < 8; i++)
#pragma unroll
        for (int j = 0; j < 4; j++) acc[i][j] = 0.f;

    for (int sub = 0; sub < 8; ++sub) {
        const int k0 = ks * 256 + sub * 32;
        __syncthreads();
#pragma unroll
        for (int j = 0; j < 4; ++j) {
            int e = t + j * 256, row = e >> 3, c4 = e & 7;
            float4 v = *(const float4*)&W_img[(size_t)(d0 + row) * E_ + k0 + c4 * 4];
            Wt[row][c4 * 4 + 0] = v.x; Wt[row][c4 * 4 + 1] = v.y;
            Wt[row][c4 * 4 + 2] = v.z; Wt[row][c4 * 4 + 3] = v.w;
        }
#pragma unroll
        for (int j = 0; j < 2; ++j) {
            int e = t + j * 256, row = e >> 3, c4 = e & 7;
            int src = row * C_ + g_idx[row];
            float4 v = *(const float4*)&x_img[(size_t)src * E_ + k0 + c4 * 4];
            Xt[row][c4 * 4 + 0] = v.x; Xt[row][c4 * 4 + 1] = v.y;
            Xt[row][c4 * 4 + 2] = v.z; Xt[row][c4 * 4 + 3] = v.w;
        }
        __syncthreads();
#pragma unroll 8
        for (int k = 0; k < 32; ++k) {
            float xv[4];
#pragma unroll
            for (int j = 0; j < 4; j++) xv[j] = Xt[bg * 4 + j][k];
#pragma unroll
            for (int i = 0; i < 8; i++) {
                float wv = Wt[dg + i * 16][k];
#pragma unroll
                for (int j = 0; j < 4; j++) acc[i][j] += wv * xv[j];
            }
        }
    }
    float* outp = g_ldrp + (size_t)ks * (B_ * D_);
#pragma unroll
    for (int i = 0; i < 8; i++)
#pragma unroll
        for (int j = 0; j < 4; j++)
            outp[(bg * 4 + j) * D_ + d0 + dg + i * 16] = acc[i][j];
}

__global__ void __launch_bounds__(256) k2b_reduce(const float* __restrict__ b_img) {
    int i = blockIdx.x * 256 + threadIdx.x;
    float s = b_img[i & (D_ - 1)];
#pragma unroll
    for (int ks = 0; ks < 8; ++ks) s += g_ldrp[ks * (B_ * D_) + i];
    g_ldr[i] = s;
}

// ========== K3: fused bf16 GEMM (mma.sync) -> g_dpp, g_sqp ================
// Grid = 2048 CTAs: 128 m-tiles x 16 n-tiles. CTA tile M=128 x N=128 over
// full K=2048, BK=64, 3-stage cp.async pipeline, one __syncthreads/stage.
// Warp tile M32 x N64, __launch_bounds__(256, 2) -> 2 CTAs/SM (16 warps).
// R16 tweak vs R13: the next-stage cp.async burst is issued AFTER the first
// ks-step, so MMAs start immediately at barrier exit and the LSU burst is
// hidden under tensor work. Everything else identical to R13.
#define ROWB   144                   // bytes per smem row (64 bf16 + pad)
#define STG_A  (128 * ROWB)          // 18432 B
#define STG_B  (128 * ROWB)          // 18432 B
#define KSTEPS 32                    // 32 k-steps of BK=64
#define SMEM_DYN (3 * (STG_A + STG_B))   // 110592 B

__device__ __forceinline__ void k3_load_stage(uint32_t sA, uint32_t sB, int s,
                                              const __nv_bfloat16* Abase,
                                              const __nv_bfloat16* Bbase, int t) {
    const int k0 = s * 64;
    const uint32_t aB = sA + (s % 3) * STG_A;
    const uint32_t bB = sB + (s % 3) * STG_B;
    const __nv_bfloat16* Ag = Abase + k0;
    const __nv_bfloat16* Bg = Bbase + k0;
#pragma unroll
    for (int j = 0; j < 4; ++j) {                  // A: 128 rows x 8 chunks
        int id = j * 256 + t, row = id >> 3, ch = id & 7;
        CP16(aB + row * ROWB + ch * 16, Ag + (size_t)row * E_ + ch * 8);
    }
#pragma unroll
    for (int j = 0; j < 4; ++j) {                  // B: 128 rows x 8 chunks
        int id = j * 256 + t, row = id >> 3, ch = id & 7;
        CP16(bB + row * ROWB + ch * 16, Bg + (size_t)row * E_ + ch * 8);
    }
    CP_COMMIT();
}

// One ks-step: 2 A-LDSM.x4 + 4 B-LDSM.x4, then 16 MMAs.
__device__ __forceinline__ void k3_step(float acc[2][8][4], uint32_t aB, uint32_t bB,
                                        int ks, int mrow, int ncol, int lane) {
    uint32_t a[2][4];
    uint32_t b[4][4];
#pragma unroll
    for (int mi = 0; mi < 2; ++mi) {
        uint32_t addr = aB + (mrow + mi * 16 + (lane & 15)) * ROWB
                      + ks * 32 + ((lane >> 4) << 4);
        asm volatile("ldmatrix.sync.aligned.m8n8.x4.shared.b16 {%0,%1,%2,%3}, [%4];"
                     : "=r"(a[mi][0]), "=r"(a[mi][1]), "=r"(a[mi][2]), "=r"(a[mi][3])
                     : "r"(addr));
    }
#pragma unroll
    for (int ng = 0; ng < 4; ++ng) {
        uint32_t addr = bB + (ncol + ng * 16 + ((lane >> 4) << 3) + (lane & 7)) * ROWB
                      + ks * 32 + (((lane >> 3) & 1) << 4);
        asm volatile("ldmatrix.sync.aligned.m8n8.x4.shared.b16 {%0,%1,%2,%3}, [%4];"
                     : "=r"(b[ng][0]), "=r"(b[ng][1]), "=r"(b[ng][2]), "=r"(b[ng][3])
                     : "r"(addr));
    }
#pragma unroll
    for (int ng = 0; ng < 4; ++ng) {
#pragma unroll
        for (int mi = 0; mi < 2; ++mi) {
            asm volatile("mma.sync.aligned.m16n8k16.row.col.f32.bf16.bf16.f32 "
                         "{%0,%1,%2,%3}, {%4,%5,%6,%7}, {%8,%9}, {%0,%1,%2,%3};"
                         : "+f"(acc[mi][ng * 2][0]), "+f"(acc[mi][ng * 2][1]),
                           "+f"(acc[mi][ng * 2][2]), "+f"(acc[mi][ng * 2][3])
                         : "r"(a[mi][0]), "r"(a[mi][1]), "r"(a[mi][2]), "r"(a[mi][3]),
                           "r"(b[ng][0]), "r"(b[ng][1]));
            asm volatile("mma.sync.aligned.m16n8k16.row.col.f32.bf16.bf16.f32 "
                         "{%0,%1,%2,%3}, {%4,%5,%6,%7}, {%8,%9}, {%0,%1,%2,%3};"
                         : "+f"(acc[mi][ng * 2 + 1][0]), "+f"(acc[mi][ng * 2 + 1][1]),
                           "+f"(acc[mi][ng * 2 + 1][2]), "+f"(acc[mi][ng * 2 + 1][3])
                         : "r"(a[mi][0]), "r"(a[mi][1]), "r"(a[mi][2]), "r"(a[mi][3]),
                           "r"(b[ng][2]), "r"(b[ng][3]));
        }
    }
}

__global__ void __launch_bounds__(256, 2) k3_gemm(const float* __restrict__ bwrd) {
    extern __shared__ __align__(16) char dyn[];
    __shared__ float sDp[2][128], sSq[2][128];

    const int t = threadIdx.x, lane = t & 31, warp = t >> 5;
    const int u = blockIdx.x;
    const int mt = u >> 4;                         // 0..127 m-tile
    const int nt = u & 15;                         // 0..15 n-tile (fixed per CTA)
    const int m0 = mt * 128;
    const int n0 = nt * 128;
    const int bidx = mt >> 1;                      // batch index
    const int mrow = (warp & 3) * 32;              // warp m-origin (M32)
    const int wn = warp >> 2;                      // 0..1
    const int ncol = wn * 64;                      // warp n-origin (N64)
    const __nv_bfloat16* Abase = g_xbf + (size_t)m0 * E_;
    const __nv_bfloat16* Bbase = g_wbf + (size_t)n0 * E_;
    const float* ldrb = g_ldr + bidx * D_;

    const uint32_t sA = smem_u32(dyn);
    const uint32_t sB = sA + 3 * STG_A;

    float acc[2][8][4];                            // mi(2 x m16) x nj(8 x n8) x frag
#pragma unroll
    for (int mi = 0; mi < 2; ++mi)
#pragma unroll
        for (int nj = 0; nj < 8; ++nj)
#pragma unroll
            for (int c = 0; c < 4; ++c) acc[mi][nj][c] = 0.f;

    k3_load_stage(sA, sB, 0, Abase, Bbase, t);
    k3_load_stage(sA, sB, 1, Abase, Bbase, t);

#pragma unroll 1
    for (int s = 0; s < KSTEPS; ++s) {
        if (s + 1 < KSTEPS) CP_WAIT1(); else CP_WAIT0();
        __syncthreads();

        const uint32_t aB = sA + (s % 3) * STG_A;
        const uint32_t bB = sB + (s % 3) * STG_B;

        // first ks-step immediately at barrier exit: tensor pipe starts now
        k3_step(acc, aB, bB, 0, mrow, ncol, lane);
        // next-stage cp.async burst issued under the running MMA window
        if (s + 2 < KSTEPS) k3_load_stage(sA, sB, s + 2, Abase, Bbase, t);
#pragma unroll
        for (int ks = 1; ks < 4; ++ks)
            k3_step(acc, aB, bB, ks, mrow, ncol, lane);
    }

    // -------- fused epilogue (once per CTA): bias + dp/sq ----------------
    float dp[4], sq[4];
#pragma unroll
    for (int i = 0; i < 4; ++i) { dp[i] = 0.f; sq[i] = 0.f; }
#pragma unroll
    for (int nj = 0; nj < 8; ++nj) {
        const int n = n0 + ncol + nj * 8 + (lane & 3) * 2;
        const float bi0 = bwrd[n], bi1 = bwrd[n + 1];
        const float l0 = ldrb[n], l1 = ldrb[n + 1];
#pragma unroll
        for (int mi = 0; mi < 2; ++mi) {
            float v0 = acc[mi][nj][0] + bi0;
            float v1 = acc[mi][nj][1] + bi1;
            float v2 = acc[mi][nj][2] + bi0;
            float v3 = acc[mi][nj][3] + bi1;
            dp[mi * 2 + 0] = fmaf(v0, l0, dp[mi * 2 + 0]);
            dp[mi * 2 + 0] = fmaf(v1, l1, dp[mi * 2 + 0]);
            sq[mi * 2 + 0] = fmaf(v0, v0, sq[mi * 2 + 0]);
            sq[mi * 2 + 0] = fmaf(v1, v1, sq[mi * 2 + 0]);
            dp[mi * 2 + 1] = fmaf(v2, l0, dp[mi * 2 + 1]);
            dp[mi * 2 + 1] = fmaf(v3, l1, dp[mi * 2 + 1]);
            sq[mi * 2 + 1] = fmaf(v2, v2, sq[mi * 2 + 1]);
            sq[mi * 2 + 1] = fmaf(v3, v3, sq[mi * 2 + 1]);
        }
    }

    // reduce the 4 lanes (lane&3) sharing each row, then combine n-groups
#pragma unroll
    for (int off = 1; off < 4; off <<= 1) {
#pragma unroll
        for (int i = 0; i < 4; ++i) {
            dp[i] += __shfl_xor_sync(0xffffffffu, dp[i], off);
            sq[i] += __shfl_xor_sync(0xffffffffu, sq[i], off);
        }
    }
    if ((lane & 3) == 0) {
#pragma unroll
        for (int mi = 0; mi < 2; ++mi)
#pragma unroll
            for (int p = 0; p < 2; ++p) {
                int r = mrow + mi * 16 + (lane >> 2) + p * 8;
                sDp[wn][r] = dp[mi * 2 + p];
                sSq[wn][r] = sq[mi * 2 + p];
            }
    }
    __syncthreads();
    if (t < 128) {
        g_dpp[nt][m0 + t] = sDp[0][t] + sDp[1][t];
        g_sqp[nt][m0 + t] = sSq[0][t] + sSq[1][t];
    }
}

// ================= K4: combine partials + norm + cosine + softmax =========
__global__ void __launch_bounds__(256) k4_softmax(float* __restrict__ out) {
    __shared__ float red[256];
    __shared__ float bcast;
    const int b = blockIdx.x, t = threadIdx.x;
    float s = 0.f;
    for (int i = t; i < D_; i += 256) { float v = g_ldr[b * D_ + i]; s += v * v; }
    red[t] = s; __syncthreads();
    for (int st = 128; st > 0; st >>= 1) { if (t < st) red[t] += red[t + st]; __syncthreads(); }
    if (t == 0) bcast = sqrtf(red[0]);
    __syncthreads();
    const float lnorm = bcast;
    const int m = b * W_ + t;
    float dpv = 0.f, sqv = 0.f;
#pragma unroll
    for (int ntl = 0; ntl < 16; ++ntl) { dpv += g_dpp[ntl][m]; sqv += g_sqp[ntl][m]; }
    float dn = lnorm * sqrtf(fmaxf(sqv, 0.f));
    float logit = dpv / fmaxf(dn, 1e-8f);
    __syncthreads();
    red[t] = logit; __syncthreads();
    for (int st = 128; st > 0; st >>= 1) { if (t < st) red[t] = fmaxf(red[t], red[t + st]); __syncthreads(); }
    float mx = red[0]; __syncthreads();
    float e = expf(logit - mx);
    red[t] = e; __syncthreads();
    for (int st = 128; st > 0; st >>= 1) { if (t < st) red[t] += red[t + st]; __syncthreads(); }
    out[m] = e / red[0];
}

// ===========================================================================
extern "C" void kernel_launch(void* const* d_in, const int* in_sizes, int n_in,
                              void* d_out, int out_size) {
    const float* x_img = (const float*)d_in[0];   // [64,256,2048]
    const float* x_txt = (const float*)d_in[1];   // [64,256,2048]
    const float* y     = (const float*)d_in[2];   // [64,256]
    const float* W_img = (const float*)d_in[3];   // [2048,2048]
    const float* b_img = (const float*)d_in[4];   // [2048]
    const float* W_wrd = (const float*)d_in[5];   // [2048,2048]
    const float* b_wrd = (const float*)d_in[6];   // [2048]
    float* out = (float*)d_out;                   // [64,256]

    cudaFuncSetAttribute(k3_gemm, cudaFuncAttributeMaxDynamicSharedMemorySize, SMEM_DYN);

    k1_prep<<<2048, 256>>>(y, x_txt, W_wrd);
    k2_leader<<<dim3(16, 8), 256>>>(x_img, W_img);
    k2b_reduce<<<512, 256>>>(b_img);
    k3_gemm<<<2048, 256, SMEM_DYN>>>(b_wrd);
    k4_softmax<<<B_, 256>>>(out);
}